// round 5
// baseline (speedup 1.0000x reference)
#include <cuda_runtime.h>
#include <cuda_bf16.h>
#include <cstdint>

#define BATCH 32768
#define HDIM  1024
#define NFAM  10

// ---------------------------------------------------------------- scratch
__device__ __align__(16) int            g_nearest[BATCH];
__device__ __align__(16) float          g_protoW1[NFAM * HDIM];
__device__ __align__(16) float          g_pp[NFAM];
__device__ __align__(16) __nv_bfloat16  g_feat_hi[(size_t)BATCH * HDIM];
__device__ __align__(16) __nv_bfloat16  g_feat_lo[(size_t)BATCH * HDIM];
__device__ __align__(16) __nv_bfloat16  g_hid_hi[(size_t)BATCH * HDIM];
__device__ __align__(16) __nv_bfloat16  g_hid_lo[(size_t)BATCH * HDIM];
__device__ __align__(16) __nv_bfloat16  g_w1t_hi[HDIM * HDIM];
__device__ __align__(16) __nv_bfloat16  g_w1t_lo[HDIM * HDIM];
__device__ __align__(16) __nv_bfloat16  g_w2t_hi[HDIM * HDIM];
__device__ __align__(16) __nv_bfloat16  g_w2t_lo[HDIM * HDIM];

// ---------------------------------------------------------------- helpers
__device__ __forceinline__ uint32_t smem_u32(const void* p) {
    uint32_t a;
    asm("{ .reg .u64 t; cvta.to.shared.u64 t, %1; cvt.u32.u64 %0, t; }" : "=r"(a) : "l"(p));
    return a;
}
__device__ __forceinline__ void cp16(uint32_t dst, const void* src) {
    asm volatile("cp.async.cg.shared.global [%0], [%1], 16;" :: "r"(dst), "l"(src) : "memory");
}
#define CP_COMMIT() asm volatile("cp.async.commit_group;" ::: "memory")
#define CP_WAIT1()  asm volatile("cp.async.wait_group 1;"  ::: "memory")

__device__ __forceinline__ void ldsm4(uint32_t& r0, uint32_t& r1, uint32_t& r2, uint32_t& r3,
                                      uint32_t addr) {
    asm volatile("ldmatrix.sync.aligned.m8n8.x4.shared.b16 {%0,%1,%2,%3}, [%4];"
                 : "=r"(r0), "=r"(r1), "=r"(r2), "=r"(r3) : "r"(addr));
}
__device__ __forceinline__ void mma16816(float* c, uint32_t a0, uint32_t a1, uint32_t a2,
                                         uint32_t a3, uint32_t b0, uint32_t b1) {
    asm volatile("mma.sync.aligned.m16n8k16.row.col.f32.bf16.bf16.f32 "
                 "{%0,%1,%2,%3}, {%4,%5,%6,%7}, {%8,%9}, {%0,%1,%2,%3};"
                 : "+f"(c[0]), "+f"(c[1]), "+f"(c[2]), "+f"(c[3])
                 : "r"(a0), "r"(a1), "r"(a2), "r"(a3), "r"(b0), "r"(b1));
}

__device__ __forceinline__ void split2(float v, __nv_bfloat16& h, __nv_bfloat16& l) {
    h = __float2bfloat16(v);
    l = __float2bfloat16(v - __bfloat162float(h));
}

// ---------------------------------------------------------------- prep kernels
// pp[j] = sum_h protos[j][h]^2
__global__ void pp_kernel(const float* __restrict__ protos) {
    const int j = threadIdx.x >> 5, lane = threadIdx.x & 31;
    if (j < NFAM) {
        float s = 0.f;
        for (int h = lane; h < HDIM; h += 32) {
            const float p = protos[j * HDIM + h];
            s = fmaf(p, p, s);
        }
#pragma unroll
        for (int o = 16; o > 0; o >>= 1) s += __shfl_xor_sync(0xffffffffu, s, o);
        if (lane == 0) g_pp[j] = s;
    }
}

// Fused: split features into bf16 hi/lo AND compute nearest prototype.
// Block: 256 threads = 8 warps; each warp handles 4 rows. Grid: BATCH/32.
__global__ __launch_bounds__(256) void argsplit_kernel(const float* __restrict__ feat,
                                                       const float* __restrict__ protos) {
    __shared__ float4 sp4[NFAM * 256];   // 40 KB
    for (int i = threadIdx.x; i < NFAM * 256; i += 256)
        sp4[i] = reinterpret_cast<const float4*>(protos)[i];
    __syncthreads();

    const int warp = threadIdx.x >> 5, lane = threadIdx.x & 31;
    const int row0 = (blockIdx.x * 8 + warp) * 4;

    float dot[NFAM][4];
#pragma unroll
    for (int j = 0; j < NFAM; ++j)
#pragma unroll
        for (int r = 0; r < 4; ++r) dot[j][r] = 0.f;

    for (int t = 0; t < 8; ++t) {
        const int idx = lane + 32 * t;       // float4 index within row
        float4 fv[4];
#pragma unroll
        for (int r = 0; r < 4; ++r)
            fv[r] = reinterpret_cast<const float4*>(feat)[(size_t)(row0 + r) * 256 + idx];

        // split + store bf16 hi/lo
#pragma unroll
        for (int r = 0; r < 4; ++r) {
            __nv_bfloat16 h0, h1, h2, h3, l0, l1, l2, l3;
            split2(fv[r].x, h0, l0); split2(fv[r].y, h1, l1);
            split2(fv[r].z, h2, l2); split2(fv[r].w, h3, l3);
            const size_t off = (size_t)(row0 + r) * 256 + idx;   // uint2 index (4 bf16)
            uint2 hv, lv;
            hv.x = (uint32_t)__bfloat16_as_ushort(h0) | ((uint32_t)__bfloat16_as_ushort(h1) << 16);
            hv.y = (uint32_t)__bfloat16_as_ushort(h2) | ((uint32_t)__bfloat16_as_ushort(h3) << 16);
            lv.x = (uint32_t)__bfloat16_as_ushort(l0) | ((uint32_t)__bfloat16_as_ushort(l1) << 16);
            lv.y = (uint32_t)__bfloat16_as_ushort(l2) | ((uint32_t)__bfloat16_as_ushort(l3) << 16);
            reinterpret_cast<uint2*>(g_feat_hi)[off] = hv;
            reinterpret_cast<uint2*>(g_feat_lo)[off] = lv;
        }

        // dots with all prototypes
#pragma unroll
        for (int j = 0; j < NFAM; ++j) {
            const float4 p = sp4[j * 256 + idx];
#pragma unroll
            for (int r = 0; r < 4; ++r) {
                float d = dot[j][r];
                d = fmaf(p.x, fv[r].x, d);
                d = fmaf(p.y, fv[r].y, d);
                d = fmaf(p.z, fv[r].z, d);
                d = fmaf(p.w, fv[r].w, d);
                dot[j][r] = d;
            }
        }
    }
#pragma unroll
    for (int j = 0; j < NFAM; ++j)
#pragma unroll
        for (int r = 0; r < 4; ++r)
#pragma unroll
            for (int o = 16; o > 0; o >>= 1)
                dot[j][r] += __shfl_xor_sync(0xffffffffu, dot[j][r], o);

    if (lane < 4) {
        const int r = lane;
        float best = g_pp[0] - 2.f * dot[0][r];
        int bi = 0;
#pragma unroll
        for (int j = 1; j < NFAM; ++j) {
            const float d = g_pp[j] - 2.f * dot[j][r];
            if (d < best) { best = d; bi = j; }
        }
        g_nearest[row0 + r] = bi;
    }
}

// transpose + split: dst_hi[n*1024+k] = split(W[k*1024+n]).  WHICH: 0 -> w1t, 1 -> w2t.
template <int WHICH>
__global__ __launch_bounds__(256) void tsplit_kernel(const float* __restrict__ W) {
    __nv_bfloat16* thi = (WHICH == 0) ? g_w1t_hi : g_w2t_hi;
    __nv_bfloat16* tlo = (WHICH == 0) ? g_w1t_lo : g_w2t_lo;
    __shared__ float t[32][33];
    const int bx = blockIdx.x * 32, by = blockIdx.y * 32;
    const int tx = threadIdx.x, ty = threadIdx.y;   // (32, 8)
#pragma unroll
    for (int j = 0; j < 4; ++j)
        t[ty + 8 * j][tx] = W[(size_t)(by + ty + 8 * j) * HDIM + bx + tx];
    __syncthreads();
#pragma unroll
    for (int j = 0; j < 4; ++j) {
        float v = t[tx][ty + 8 * j];
        __nv_bfloat16 h, l; split2(v, h, l);
        thi[(size_t)(bx + ty + 8 * j) * HDIM + by + tx] = h;
        tlo[(size_t)(bx + ty + 8 * j) * HDIM + by + tx] = l;
    }
}

// protoW1[j][n] = b1[n] + protos[j] . W1[H + :, n]
__global__ __launch_bounds__(256) void protow1_kernel(const float* __restrict__ protos,
                                                      const float* __restrict__ W1,
                                                      const float* __restrict__ b1) {
    const int n = blockIdx.x * 256 + threadIdx.x;
    const int j = blockIdx.y;
    const float* p = protos + j * HDIM;
    const float* w = W1 + (size_t)HDIM * HDIM + n;
    float acc = b1[n];
#pragma unroll 8
    for (int h = 0; h < HDIM; ++h) acc = fmaf(p[h], w[(size_t)h * HDIM], acc);
    g_protoW1[j * HDIM + n] = acc;
}

// ---------------------------------------------------------------- HMMA GEMM
// Block tile 128(M) x 256(N), 8 warps as 2(M) x 4(N), warp tile 64x64.
// K split segments: (Ah,Bh), (Al,Bh), (Ah,Bl) -> K_total = 3072, BK = 32 -> 96 slices.
#define ROWB   80                      // padded row stride (32 bf16 + 16B pad)
#define ASTAGE (128 * ROWB)            // 10240
#define BSTAGE (256 * ROWB)            // 20480
#define STAGEB (ASTAGE + BSTAGE)       // 30720
#define NSTG   3
#define GSMEM  (NSTG * STAGEB)         // 92160

template <bool FUSE1>
__global__ __launch_bounds__(256, 1) void hmma_gemm_kernel(const float* __restrict__ b2,
                                                           float* __restrict__ out) {
    const __nv_bfloat16* __restrict__ Ahi = FUSE1 ? g_feat_hi : g_hid_hi;
    const __nv_bfloat16* __restrict__ Alo = FUSE1 ? g_feat_lo : g_hid_lo;
    const __nv_bfloat16* __restrict__ Bhi = FUSE1 ? g_w1t_hi : g_w2t_hi;
    const __nv_bfloat16* __restrict__ Blo = FUSE1 ? g_w1t_lo : g_w2t_lo;

    extern __shared__ char sm[];
    const uint32_t smBase = smem_u32(sm);

    const int tid  = threadIdx.x;
    const int lane = tid & 31;
    const int wid  = tid >> 5;
    const int wm   = (wid & 1) * 64;     // warp M offset
    const int wn   = (wid >> 1) * 64;    // warp N offset
    const int bm   = blockIdx.y * 128;
    const int bn   = blockIdx.x * 256;

    auto load_stage = [&](int s, int buf) {
        const int seg = s >> 5;
        const __nv_bfloat16* gA = (seg == 1) ? Alo : Ahi;
        const __nv_bfloat16* gB = (seg == 2) ? Blo : Bhi;
        const int ke = (s & 31) * 32;
        const uint32_t dA = smBase + buf * STAGEB;
        const uint32_t dB = dA + ASTAGE;
        // A: 512 chunks of 16B (128 rows x 4)
#pragma unroll
        for (int i = 0; i < 2; ++i) {
            const int c = tid + 256 * i;
            const int row = c >> 2, k = c & 3;
            cp16(dA + row * ROWB + k * 16, gA + (size_t)(bm + row) * HDIM + ke + k * 8);
        }
        // B: 1024 chunks (256 rows x 4)
#pragma unroll
        for (int i = 0; i < 4; ++i) {
            const int c = tid + 256 * i;
            const int row = c >> 2, k = c & 3;
            cp16(dB + row * ROWB + k * 16, gB + (size_t)(bn + row) * HDIM + ke + k * 8);
        }
    };

    float acc[4][8][4];
#pragma unroll
    for (int i = 0; i < 4; ++i)
#pragma unroll
        for (int j = 0; j < 8; ++j)
#pragma unroll
            for (int k = 0; k < 4; ++k) acc[i][j][k] = 0.f;

    const uint32_t aAddr0 = smBase + (wm + (lane & 15)) * ROWB + (lane >> 4) * 16;
    const uint32_t bAddr0 = smBase + ASTAGE + (wn + (lane & 7) + ((lane >> 4) << 3)) * ROWB
                                   + (((lane >> 3) & 1) << 4);

    load_stage(0, 0); CP_COMMIT();
    load_stage(1, 1); CP_COMMIT();

    for (int s = 0; s < 96; ++s) {
        CP_WAIT1();
        __syncthreads();
        if (s + 2 < 96) load_stage(s + 2, (s + 2) % NSTG);
        CP_COMMIT();

        const int buf = s % NSTG;
        const uint32_t aB = aAddr0 + buf * STAGEB;
        const uint32_t bB = bAddr0 + buf * STAGEB;
#pragma unroll
        for (int ks = 0; ks < 2; ++ks) {
            const int ko = ks * 32;
            uint32_t a[4][4];
#pragma unroll
            for (int mt = 0; mt < 4; ++mt)
                ldsm4(a[mt][0], a[mt][1], a[mt][2], a[mt][3], aB + mt * 16 * ROWB + ko);
            uint32_t b[4][4];
#pragma unroll
            for (int g = 0; g < 4; ++g)
                ldsm4(b[g][0], b[g][1], b[g][2], b[g][3], bB + g * 16 * ROWB + ko);
#pragma unroll
            for (int mt = 0; mt < 4; ++mt)
#pragma unroll
                for (int g = 0; g < 4; ++g) {
                    mma16816(acc[mt][g * 2 + 0], a[mt][0], a[mt][1], a[mt][2], a[mt][3],
                             b[g][0], b[g][1]);
                    mma16816(acc[mt][g * 2 + 1], a[mt][0], a[mt][1], a[mt][2], a[mt][3],
                             b[g][2], b[g][3]);
                }
        }
    }

    // ---------------- epilogue ----------------
    const int grp = lane >> 2;      // row within m8
    const int tig = lane & 3;       // col pair
#pragma unroll
    for (int mt = 0; mt < 4; ++mt) {
        const int r0 = bm + wm + mt * 16 + grp;
        const int r1 = r0 + 8;
        const float* av0;
        const float* av1;
        if (FUSE1) {
            av0 = g_protoW1 + (size_t)g_nearest[r0] * HDIM;
            av1 = g_protoW1 + (size_t)g_nearest[r1] * HDIM;
        } else {
            av0 = b2; av1 = b2;
        }
#pragma unroll
        for (int gg = 0; gg < 8; ++gg) {
            const int col = bn + wn + (gg >> 1) * 16 + (gg & 1) * 8 + tig * 2;
            const float2 p0 = *reinterpret_cast<const float2*>(av0 + col);
            const float2 p1 = *reinterpret_cast<const float2*>(av1 + col);
            float v00 = acc[mt][gg][0] + p0.x, v01 = acc[mt][gg][1] + p0.y;
            float v10 = acc[mt][gg][2] + p1.x, v11 = acc[mt][gg][3] + p1.y;
            if (FUSE1) {
                v00 = fmaxf(v00, 0.f); v01 = fmaxf(v01, 0.f);
                v10 = fmaxf(v10, 0.f); v11 = fmaxf(v11, 0.f);
                __nv_bfloat16 h0, h1, h2, h3, l0, l1, l2, l3;
                split2(v00, h0, l0); split2(v01, h1, l1);
                split2(v10, h2, l2); split2(v11, h3, l3);
                *reinterpret_cast<__nv_bfloat162*>(g_hid_hi + (size_t)r0 * HDIM + col) = __nv_bfloat162(h0, h1);
                *reinterpret_cast<__nv_bfloat162*>(g_hid_lo + (size_t)r0 * HDIM + col) = __nv_bfloat162(l0, l1);
                *reinterpret_cast<__nv_bfloat162*>(g_hid_hi + (size_t)r1 * HDIM + col) = __nv_bfloat162(h2, h3);
                *reinterpret_cast<__nv_bfloat162*>(g_hid_lo + (size_t)r1 * HDIM + col) = __nv_bfloat162(l2, l3);
            } else {
                *reinterpret_cast<float2*>(out + (size_t)r0 * HDIM + col) = make_float2(v00, v01);
                *reinterpret_cast<float2*>(out + (size_t)r1 * HDIM + col) = make_float2(v10, v11);
            }
        }
    }
}

// ---------------------------------------------------------------- launch
extern "C" void kernel_launch(void* const* d_in, const int* in_sizes, int n_in,
                              void* d_out, int out_size) {
    (void)in_sizes; (void)n_in; (void)out_size;
    const float* features = (const float*)d_in[0];
    const float* protos   = (const float*)d_in[1];
    const float* W1       = (const float*)d_in[2];
    const float* b1       = (const float*)d_in[3];
    const float* W2       = (const float*)d_in[4];
    const float* b2       = (const float*)d_in[5];
    float* out = (float*)d_out;

    cudaFuncSetAttribute(hmma_gemm_kernel<true>,  cudaFuncAttributeMaxDynamicSharedMemorySize, GSMEM);
    cudaFuncSetAttribute(hmma_gemm_kernel<false>, cudaFuncAttributeMaxDynamicSharedMemorySize, GSMEM);

    pp_kernel<<<1, 320>>>(protos);
    argsplit_kernel<<<BATCH / 32, 256>>>(features, protos);
    tsplit_kernel<0><<<dim3(32, 32), dim3(32, 8)>>>(W1);
    tsplit_kernel<1><<<dim3(32, 32), dim3(32, 8)>>>(W2);
    protow1_kernel<<<dim3(HDIM / 256, NFAM), 256>>>(protos, W1, b1);

    dim3 grid(HDIM / 256, BATCH / 128);   // (4, 256)
    hmma_gemm_kernel<true><<<grid, 256, GSMEM>>>(nullptr, nullptr);
    hmma_gemm_kernel<false><<<grid, 256, GSMEM>>>(b2, out);
}